// round 2
// baseline (speedup 1.0000x reference)
#include <cuda_runtime.h>
#include <math.h>

#define BATCH 16
#define NPART 256
#define DMODEL 128
#define NHEAD 8
#define HDIM 16
#define NTILES 16           // NPART / 16
#define NTRI 136            // NTILES*(NTILES+1)/2

#define PI_F 3.14159265358979323846f
#define TWO_PI_F 6.28318530717958647692f
#define INV_TWO_PI_F 0.15915494309189533577f
#define EPS_F 1e-8f

// ---------------- scratch (device globals; no runtime allocation) ----------------
__device__ float g_bias[BATCH * NHEAD * NPART * NPART]; // [b][h][j][i] = attn_bias[b,h,i,j]
__device__ float g_q[BATCH * NPART * DMODEL];
__device__ float g_k[BATCH * NPART * DMODEL];
__device__ float g_v[BATCH * NPART * DMODEL];
__device__ float g_attn[BATCH * NPART * DMODEL];

// gelu(x) with tanh approximation (matches jax.nn.gelu approximate=True):
// 0.5*x*(1+tanh(u)) == x * sigmoid(2u) == x / (1 + exp(-2u))
__device__ __forceinline__ float gelu_f(float x) {
    float u = 0.7978845608028654f * (x + 0.044715f * x * x * x);
    return x / (1.0f + __expf(-2.0f * u));
}

// ---------------- pair MLP layer: sA[64][256] x W[64][64] -> gelu -> sA in-place ----
__device__ __forceinline__ void mlp_layer(float* sA, const float* __restrict__ W,
                                          const float* __restrict__ Bs, int tid) {
    const int tn = tid & 7;      // 8 col groups of 8
    const int tp = tid >> 3;     // 32 pair groups of 8
    const int n0 = tn * 8, p0 = tp * 8;
    float acc[8][8];
#pragma unroll
    for (int nn = 0; nn < 8; nn++) {
        float bv = Bs[n0 + nn];
#pragma unroll
        for (int pp = 0; pp < 8; pp++) acc[pp][nn] = bv;
    }
#pragma unroll 4
    for (int k = 0; k < 64; k++) {
        float4 a0 = *(const float4*)(sA + k * 256 + p0);
        float4 a1 = *(const float4*)(sA + k * 256 + p0 + 4);
        float4 w0 = __ldg((const float4*)(W + k * 64 + n0));
        float4 w1 = __ldg((const float4*)(W + k * 64 + n0 + 4));
        float a[8] = {a0.x, a0.y, a0.z, a0.w, a1.x, a1.y, a1.z, a1.w};
        float w[8] = {w0.x, w0.y, w0.z, w0.w, w1.x, w1.y, w1.z, w1.w};
#pragma unroll
        for (int pp = 0; pp < 8; pp++)
#pragma unroll
            for (int nn = 0; nn < 8; nn++)
                acc[pp][nn] = fmaf(a[pp], w[nn], acc[pp][nn]);
    }
    __syncthreads();  // all reads of sA done before overwrite
#pragma unroll
    for (int nn = 0; nn < 8; nn++) {
        int n = n0 + nn;
        float4 v0 = make_float4(gelu_f(acc[0][nn]), gelu_f(acc[1][nn]),
                                gelu_f(acc[2][nn]), gelu_f(acc[3][nn]));
        float4 v1 = make_float4(gelu_f(acc[4][nn]), gelu_f(acc[5][nn]),
                                gelu_f(acc[6][nn]), gelu_f(acc[7][nn]));
        *(float4*)(sA + n * 256 + p0) = v0;
        *(float4*)(sA + n * 256 + p0 + 4) = v1;
    }
    __syncthreads();
}

// ---------------- pairwise features + 4-layer MLP; writes attn bias -----------------
// One block = one (b, 16x16 tile of (i,j)), upper-triangular tiles only (symmetry).
__global__ __launch_bounds__(256) void pair_kernel(
    const float* __restrict__ xpf,
    const float* __restrict__ w0, const float* __restrict__ b0,
    const float* __restrict__ w1, const float* __restrict__ b1,
    const float* __restrict__ w2, const float* __restrict__ b2,
    const float* __restrict__ w3, const float* __restrict__ b3) {
    extern __shared__ float sA[];  // [64][256] activations, k-major
    __shared__ float sPt[32], sRap[32], sPhi[32], sPx[32], sPy[32], sPz[32], sE[32];
    __shared__ float sW1[256], sB1[64], sB2[64], sB3[64], sW4[512], sB4[8];

    const int tid = threadIdx.x;
    const int b = blockIdx.x / NTRI;
    int t = blockIdx.x % NTRI;
    int ti = 0, rem = t;
    while (rem >= NTILES - ti) { rem -= NTILES - ti; ti++; }
    const int tj = ti + rem;
    const int i0 = ti * 16, j0 = tj * 16;

    // stage per-particle quantities for the 16 i's and 16 j's
    if (tid < 32) {
        int l = tid & 15;
        int n = ((tid < 16) ? i0 : j0) + l;
        const float* base = xpf + b * 4 * NPART;
        float px = base[n], py = base[NPART + n], pz = base[2 * NPART + n], e = base[3 * NPART + n];
        sPx[tid] = px; sPy[tid] = py; sPz[tid] = pz; sE[tid] = e;
        sPt[tid] = sqrtf(fmaxf(px * px + py * py, EPS_F));
        sRap[tid] = 0.5f * log1pf(2.0f * pz / fmaxf(e - pz, 1e-20f));
        sPhi[tid] = atan2f(py, px);
    }
    sW1[tid] = w0[tid];                 // (4,64)
    if (tid < 64) { sB1[tid] = b0[tid]; sB2[tid] = b1[tid]; sB3[tid] = b2[tid]; }
    sW4[tid] = w3[tid];                 // (64,8) = 512 floats
    sW4[tid + 256] = w3[tid + 256];
    if (tid < 8) sB4[tid] = b3[tid];
    __syncthreads();

    // features + layer 1 (4 -> 64), one pair per thread, p = tid
    {
        int il = tid & 15, jl = tid >> 4;
        float pti = sPt[il], ptj = sPt[16 + jl];
        float drap = sRap[il] - sRap[16 + jl];
        float x = sPhi[il] - sPhi[16 + jl] + PI_F;
        float dphi = x - floorf(x * INV_TWO_PI_F) * TWO_PI_F - PI_F;
        float delta = sqrtf(drap * drap + dphi * dphi);
        float f2 = logf(fmaxf(delta, EPS_F));                      // lndelta
        float ptmin = fminf(pti, ptj);
        float f0 = logf(fmaxf(ptmin * delta, EPS_F));              // lnkt
        float f1 = logf(fmaxf(ptmin / fmaxf(pti + ptj, EPS_F), EPS_F)); // lnz
        float es = sE[il] + sE[16 + jl];
        float pxs = sPx[il] + sPx[16 + jl];
        float pys = sPy[il] + sPy[16 + jl];
        float pzs = sPz[il] + sPz[16 + jl];
        float f3 = logf(fmaxf(es * es - pxs * pxs - pys * pys - pzs * pzs, EPS_F)); // lnm2
#pragma unroll
        for (int n = 0; n < 64; n++) {
            float v = sB1[n] + f0 * sW1[n] + f1 * sW1[64 + n] + f2 * sW1[128 + n] + f3 * sW1[192 + n];
            sA[n * 256 + tid] = gelu_f(v);
        }
    }
    __syncthreads();

    // layers 2 and 3 (64 -> 64, gelu) as register-tiled GEMMs
    mlp_layer(sA, w1, sB2, tid);
    mlp_layer(sA, w2, sB3, tid);

    // layer 4 (64 -> 8), one pair per thread
    float o[8];
#pragma unroll
    for (int h = 0; h < 8; h++) o[h] = sB4[h];
    for (int k = 0; k < 64; k++) {
        float a = sA[k * 256 + tid];
#pragma unroll
        for (int h = 0; h < 8; h++) o[h] = fmaf(a, sW4[k * 8 + h], o[h]);
    }

    const int il = tid & 15, jl = tid >> 4;
    const int i = i0 + il, j = j0 + jl;
    size_t base = (size_t)b * NHEAD * NPART * NPART;
#pragma unroll
    for (int h = 0; h < 8; h++)
        g_bias[base + (size_t)h * (NPART * NPART) + j * NPART + i] = o[h];
    if (ti != tj) {  // mirror: features are symmetric in (i,j)
#pragma unroll
        for (int h = 0; h < 8; h++)
            g_bias[base + (size_t)h * (NPART * NPART) + i * NPART + j] = o[h];
    }
}

// ---------------- QKV projections: (4096x128)@(128x128) x3 + bias ------------------
__global__ __launch_bounds__(256) void qkv_kernel(
    const float* __restrict__ X,
    const float* __restrict__ wq, const float* __restrict__ wk, const float* __restrict__ wv,
    const float* __restrict__ bq, const float* __restrict__ bk, const float* __restrict__ bv) {
    __shared__ float sX[32][129];
    const int tid = threadIdx.x;
    const int row0 = blockIdx.x * 32;
    for (int idx = tid; idx < 32 * 128; idx += 256)
        sX[idx >> 7][idx & 127] = X[row0 * 128 + idx];
    __syncthreads();
    const int tc = tid & 15, tr = tid >> 4;
    const int c0 = tc * 8, ra = tr * 2;
    float aq[2][8], ak[2][8], av[2][8];
#pragma unroll
    for (int cc = 0; cc < 8; cc++) {
        float vq = bq[c0 + cc], vk = bk[c0 + cc], vv = bv[c0 + cc];
        aq[0][cc] = vq; aq[1][cc] = vq;
        ak[0][cc] = vk; ak[1][cc] = vk;
        av[0][cc] = vv; av[1][cc] = vv;
    }
#pragma unroll 2
    for (int k = 0; k < 128; k++) {
        float x0 = sX[ra][k], x1 = sX[ra + 1][k];
        float4 q0 = __ldg((const float4*)(wq + k * 128 + c0));
        float4 q1 = __ldg((const float4*)(wq + k * 128 + c0 + 4));
        float4 k0 = __ldg((const float4*)(wk + k * 128 + c0));
        float4 k1 = __ldg((const float4*)(wk + k * 128 + c0 + 4));
        float4 v0 = __ldg((const float4*)(wv + k * 128 + c0));
        float4 v1 = __ldg((const float4*)(wv + k * 128 + c0 + 4));
        float fq[8] = {q0.x, q0.y, q0.z, q0.w, q1.x, q1.y, q1.z, q1.w};
        float fk[8] = {k0.x, k0.y, k0.z, k0.w, k1.x, k1.y, k1.z, k1.w};
        float fv[8] = {v0.x, v0.y, v0.z, v0.w, v1.x, v1.y, v1.z, v1.w};
#pragma unroll
        for (int cc = 0; cc < 8; cc++) {
            aq[0][cc] = fmaf(x0, fq[cc], aq[0][cc]);
            aq[1][cc] = fmaf(x1, fq[cc], aq[1][cc]);
            ak[0][cc] = fmaf(x0, fk[cc], ak[0][cc]);
            ak[1][cc] = fmaf(x1, fk[cc], ak[1][cc]);
            av[0][cc] = fmaf(x0, fv[cc], av[0][cc]);
            av[1][cc] = fmaf(x1, fv[cc], av[1][cc]);
        }
    }
#pragma unroll
    for (int r = 0; r < 2; r++) {
        int row = row0 + ra + r;
        *(float4*)(g_q + row * 128 + c0)     = make_float4(aq[r][0], aq[r][1], aq[r][2], aq[r][3]);
        *(float4*)(g_q + row * 128 + c0 + 4) = make_float4(aq[r][4], aq[r][5], aq[r][6], aq[r][7]);
        *(float4*)(g_k + row * 128 + c0)     = make_float4(ak[r][0], ak[r][1], ak[r][2], ak[r][3]);
        *(float4*)(g_k + row * 128 + c0 + 4) = make_float4(ak[r][4], ak[r][5], ak[r][6], ak[r][7]);
        *(float4*)(g_v + row * 128 + c0)     = make_float4(av[r][0], av[r][1], av[r][2], av[r][3]);
        *(float4*)(g_v + row * 128 + c0 + 4) = make_float4(av[r][4], av[r][5], av[r][6], av[r][7]);
    }
}

// ---------------- attention: one block per (b,h), online softmax -------------------
__global__ __launch_bounds__(256) void attn_kernel() {
    __shared__ float sK[NPART * HDIM];
    __shared__ float sV[NPART * HDIM];
    const int tid = threadIdx.x;
    const int b = blockIdx.x >> 3, h = blockIdx.x & 7;

    {
        const float4* kp = (const float4*)(g_k + (b * NPART + tid) * DMODEL + h * HDIM);
        const float4* vp = (const float4*)(g_v + (b * NPART + tid) * DMODEL + h * HDIM);
        float4* kd = (float4*)(sK + tid * HDIM);
        float4* vd = (float4*)(sV + tid * HDIM);
#pragma unroll
        for (int d4 = 0; d4 < 4; d4++) { kd[d4] = kp[d4]; vd[d4] = vp[d4]; }
    }
    float q[16];
    {
        const float4* qp = (const float4*)(g_q + (b * NPART + tid) * DMODEL + h * HDIM);
#pragma unroll
        for (int d4 = 0; d4 < 4; d4++) {
            float4 v = qp[d4];
            q[d4 * 4] = v.x; q[d4 * 4 + 1] = v.y; q[d4 * 4 + 2] = v.z; q[d4 * 4 + 3] = v.w;
        }
    }
    __syncthreads();

    float m = -1e30f, l = 0.0f, acc[16];
#pragma unroll
    for (int d = 0; d < 16; d++) acc[d] = 0.0f;
    const float* bias_col = g_bias + ((size_t)(b * NHEAD + h)) * (NPART * NPART) + tid;

#pragma unroll 2
    for (int j = 0; j < NPART; j++) {
        const float4* kj = (const float4*)(sK + j * HDIM);
        float4 k0 = kj[0], k1 = kj[1], k2 = kj[2], k3 = kj[3];
        float dot = q[0] * k0.x + q[1] * k0.y + q[2] * k0.z + q[3] * k0.w
                  + q[4] * k1.x + q[5] * k1.y + q[6] * k1.z + q[7] * k1.w
                  + q[8] * k2.x + q[9] * k2.y + q[10] * k2.z + q[11] * k2.w
                  + q[12] * k3.x + q[13] * k3.y + q[14] * k3.z + q[15] * k3.w;
        float s = 0.25f * dot + bias_col[j * NPART];  // 1/sqrt(16) = 0.25
        float mn = fmaxf(m, s);
        float corr = __expf(m - mn);
        float p = __expf(s - mn);
        l = l * corr + p;
        m = mn;
        const float4* vj = (const float4*)(sV + j * HDIM);
        float4 v0 = vj[0], v1 = vj[1], v2 = vj[2], v3 = vj[3];
        float vv[16] = {v0.x, v0.y, v0.z, v0.w, v1.x, v1.y, v1.z, v1.w,
                        v2.x, v2.y, v2.z, v2.w, v3.x, v3.y, v3.z, v3.w};
#pragma unroll
        for (int d = 0; d < 16; d++) acc[d] = fmaf(acc[d], corr, p * vv[d]);
    }
    float inv = 1.0f / l;
    float* op = g_attn + (b * NPART + tid) * DMODEL + h * HDIM;
#pragma unroll
    for (int d = 0; d < 16; d++) op[d] = acc[d] * inv;
}

// ---------------- output projection: (4096x128)@(128x128) + bias -> d_out ----------
__global__ __launch_bounds__(256) void outproj_kernel(
    const float* __restrict__ wo, const float* __restrict__ bo, float* __restrict__ out) {
    __shared__ float sX[32][129];
    const int tid = threadIdx.x;
    const int row0 = blockIdx.x * 32;
    for (int idx = tid; idx < 32 * 128; idx += 256)
        sX[idx >> 7][idx & 127] = g_attn[row0 * 128 + idx];
    __syncthreads();
    const int tc = tid & 15, tr = tid >> 4;
    const int c0 = tc * 8, ra = tr * 2;
    float ao[2][8];
#pragma unroll
    for (int cc = 0; cc < 8; cc++) { float v = bo[c0 + cc]; ao[0][cc] = v; ao[1][cc] = v; }
#pragma unroll 2
    for (int k = 0; k < 128; k++) {
        float x0 = sX[ra][k], x1 = sX[ra + 1][k];
        float4 w0 = __ldg((const float4*)(wo + k * 128 + c0));
        float4 w1 = __ldg((const float4*)(wo + k * 128 + c0 + 4));
        float fw[8] = {w0.x, w0.y, w0.z, w0.w, w1.x, w1.y, w1.z, w1.w};
#pragma unroll
        for (int cc = 0; cc < 8; cc++) {
            ao[0][cc] = fmaf(x0, fw[cc], ao[0][cc]);
            ao[1][cc] = fmaf(x1, fw[cc], ao[1][cc]);
        }
    }
#pragma unroll
    for (int r = 0; r < 2; r++) {
        int row = row0 + ra + r;
        *(float4*)(out + row * 128 + c0)     = make_float4(ao[r][0], ao[r][1], ao[r][2], ao[r][3]);
        *(float4*)(out + row * 128 + c0 + 4) = make_float4(ao[r][4], ao[r][5], ao[r][6], ao[r][7]);
    }
}

extern "C" void kernel_launch(void* const* d_in, const int* in_sizes, int n_in,
                              void* d_out, int out_size) {
    const float* x_pf   = (const float*)d_in[0];
    const float* x_feat = (const float*)d_in[1];
    const float* pw0 = (const float*)d_in[2];
    const float* pb0 = (const float*)d_in[3];
    const float* pw1 = (const float*)d_in[4];
    const float* pb1 = (const float*)d_in[5];
    const float* pw2 = (const float*)d_in[6];
    const float* pb2 = (const float*)d_in[7];
    const float* pw3 = (const float*)d_in[8];
    const float* pb3 = (const float*)d_in[9];
    const float* wq = (const float*)d_in[10];
    const float* wk = (const float*)d_in[11];
    const float* wv = (const float*)d_in[12];
    const float* wo = (const float*)d_in[13];
    const float* bq = (const float*)d_in[14];
    const float* bk = (const float*)d_in[15];
    const float* bv = (const float*)d_in[16];
    const float* bo = (const float*)d_in[17];
    float* out = (float*)d_out;

    cudaFuncSetAttribute(pair_kernel, cudaFuncAttributeMaxDynamicSharedMemorySize, 65536);

    pair_kernel<<<BATCH * NTRI, 256, 65536>>>(x_pf, pw0, pb0, pw1, pb1, pw2, pb2, pw3, pb3);
    qkv_kernel<<<(BATCH * NPART) / 32, 256>>>(x_feat, wq, wk, wv, bq, bk, bv);
    attn_kernel<<<BATCH * NHEAD, 256>>>();
    outproj_kernel<<<(BATCH * NPART) / 32, 256>>>(wo, bo, out);
}